// round 9
// baseline (speedup 1.0000x reference)
#include <cuda_runtime.h>
#include <cuda_fp16.h>
#include <cstdint>

// DiscreteHawkes: T=8192, S=1024, B=8192
// out[i] = relu( mu[s_i] + beta * sum_sp D[t_i, sp] * alpha[sp, s_i] )
// where D[t,sp] = sum_{tp<t} obs[tp,sp] * exp(-beta)^(t-tp)
//
// Kernel 1 (fused prep, unchanged from R7):
//   - scan: chunked decayed scan (fp16 D), CHUNK=128, WARM=128 halo.
//   - transpose: alpha -> alphaT packed fp16.
// Kernel 2 (query): warp-private TMA bulk (cp.async.bulk) double-buffered row
//   gather into smem; dot fp16 x fp16 -> fp32. 4 queries/warp.

#define T_DIM 8192
#define S_DIM 1024
#define B_DIM 8192
#define CHUNK 128
#define WARM  128
#define NCHUNK (T_DIM / CHUNK)            // 64
#define NSCAN_BLK (NCHUNK * 4)            // 256
#define NTRANS_BLK 512

#define QK_WARPS 4
#define QK_QPW   4
#define QK_BLOCKS (B_DIM / (QK_WARPS * QK_QPW))   // 512
#define ROW_BYTES (S_DIM * 2)                     // 2048 (fp16 row)
#define STAGE_BYTES (2 * ROW_BYTES)               // 4096 (D + alphaT)

// Scratch (allocation-free rule: __device__ globals)
__device__ __half g_Dh[T_DIM * S_DIM];        // 16 MB: D[t, sp] fp16
__device__ __half g_alphaTh[S_DIM * S_DIM];   // 2 MB: alphaT[s, sp] fp16

__device__ __forceinline__ uint32_t s2u(const void* p) {
    uint32_t a;
    asm("{ .reg .u64 t; cvta.to.shared.u64 t, %1; cvt.u32.u64 %0, t; }"
        : "=r"(a) : "l"(p));
    return a;
}

// ---------------------------------------------------------------------------
// Fused prep: blocks [0, NSCAN_BLK) scan obs; the rest transpose alpha->fp16.
// ---------------------------------------------------------------------------
__global__ __launch_bounds__(256) void prep_kernel(
    const float* __restrict__ alpha,
    const int* __restrict__ obs,
    const float* __restrict__ beta) {
    if (blockIdx.x < NSCAN_BLK) {
        const int b     = blockIdx.x;
        const int chunk = b >> 2;
        const int c     = (b & 3) * 256 + threadIdx.x;
        const int tbeg  = chunk * CHUNK;
        const int t0    = (tbeg >= WARM) ? (tbeg - WARM) : 0;
        const float a   = expf(-beta[0]);

        const int* __restrict__ col = obs + c;
        __half* __restrict__ dcol = g_Dh + c;

        float d = 0.0f;
#pragma unroll 32
        for (int t = t0; t < tbeg; ++t)
            d = fmaf(a, d, a * (float)col[t * S_DIM]);
#pragma unroll 32
        for (int t = tbeg; t < tbeg + CHUNK; ++t) {
            dcol[t * S_DIM] = __float2half_rn(d);
            d = fmaf(a, d, a * (float)col[t * S_DIM]);
        }
    } else {
        __shared__ float tile[64][33];
        const int bi  = blockIdx.x - NSCAN_BLK;
        const int spb = (bi & 15) * 64;
        const int sb  = (bi >> 4) * 32;
        const int lane = threadIdx.x & 31;
        const int wrp  = threadIdx.x >> 5;
#pragma unroll
        for (int j = 0; j < 8; ++j) {
            const int r = wrp + j * 8;
            tile[r][lane] = alpha[(spb + r) * S_DIM + (sb + lane)];
        }
        __syncthreads();
        __half2* __restrict__ outh2 = reinterpret_cast<__half2*>(g_alphaTh);
#pragma unroll
        for (int j = 0; j < 4; ++j) {
            const int sl = wrp + j * 8;
            const __half2 v = __floats2half2_rn(tile[2 * lane][sl],
                                                tile[2 * lane + 1][sl]);
            outh2[(sb + sl) * (S_DIM / 2) + (spb >> 1) + lane] = v;
        }
    }
}

// ---------------------------------------------------------------------------
// Query: 4 warps/block, 4 queries/warp, warp-private 2-stage TMA-bulk ring.
// ---------------------------------------------------------------------------
__global__ __launch_bounds__(128) void query_kernel(
    const int* __restrict__ tq, const int* __restrict__ sq,
    const float* __restrict__ beta, const float* __restrict__ mu,
    float* __restrict__ out) {
    __shared__ __align__(128) unsigned char stg[QK_WARPS][2][STAGE_BYTES];
    __shared__ __align__(8)  unsigned long long mbar[QK_WARPS][2];

    const int w    = threadIdx.x >> 5;
    const int lane = threadIdx.x & 31;

    if (threadIdx.x < QK_WARPS * 2) {
        const uint32_t mb = s2u(&mbar[threadIdx.x >> 1][threadIdx.x & 1]);
        asm volatile("mbarrier.init.shared.b64 [%0], %1;"
                     :: "r"(mb), "r"(1) : "memory");
    }
    __syncthreads();

    const int qbase = (blockIdx.x * QK_WARPS + w) * QK_QPW;

    int ti[QK_QPW], si[QK_QPW];
    float bt = 0.0f;
    if (lane == 0) {
#pragma unroll
        for (int i = 0; i < QK_QPW; ++i) {
            ti[i] = tq[qbase + i];
            si[i] = sq[qbase + i];
        }
        bt = beta[0];
    }

    const char* __restrict__ dbase = (const char*)g_Dh;
    const char* __restrict__ abase = (const char*)g_alphaTh;

    // lane0 issues one query's pair of 2KB bulk copies into stage st.
    auto issue = [&](int i, int st) {
        const uint32_t mb = s2u(&mbar[w][st]);
        const uint32_t dd = s2u(&stg[w][st][0]);
        const char* dsrc = dbase + (size_t)ti[i] * ROW_BYTES;
        const char* asrc = abase + (size_t)si[i] * ROW_BYTES;
        asm volatile("mbarrier.arrive.expect_tx.shared.b64 _, [%0], %1;"
                     :: "r"(mb), "r"((uint32_t)STAGE_BYTES) : "memory");
        asm volatile(
            "cp.async.bulk.shared::cta.global.mbarrier::complete_tx::bytes "
            "[%0], [%1], %2, [%3];"
            :: "r"(dd), "l"(dsrc), "r"((uint32_t)ROW_BYTES), "r"(mb) : "memory");
        asm volatile(
            "cp.async.bulk.shared::cta.global.mbarrier::complete_tx::bytes "
            "[%0], [%1], %2, [%3];"
            :: "r"(dd + ROW_BYTES), "l"(asrc), "r"((uint32_t)ROW_BYTES), "r"(mb)
            : "memory");
    };

    if (lane == 0) {
        issue(0, 0);
        issue(1, 1);
    }

#pragma unroll
    for (int i = 0; i < QK_QPW; ++i) {
        const int st = i & 1;
        const uint32_t ph = (uint32_t)(i >> 1) & 1u;
        // wait full (acquire) — all lanes
        {
            const uint32_t mb = s2u(&mbar[w][st]);
            uint32_t done;
            asm volatile(
                "{ .reg .pred p; "
                "mbarrier.try_wait.parity.acquire.cta.shared::cta.b64 p, [%1], %2; "
                "selp.b32 %0, 1, 0, p; }"
                : "=r"(done) : "r"(mb), "r"(ph) : "memory");
            if (!done) {
                asm volatile(
                    "{ .reg .pred P1; "
                    "WAIT_%=: "
                    "mbarrier.try_wait.parity.acquire.cta.shared::cta.b64 P1, [%0], %1, 0x989680; "
                    "@P1 bra.uni DONE_%=; "
                    "bra.uni WAIT_%=; "
                    "DONE_%=: }"
                    :: "r"(mb), "r"(ph) : "memory");
            }
        }

        const uint4* du = reinterpret_cast<const uint4*>(&stg[w][st][0]);
        const uint4* au = reinterpret_cast<const uint4*>(&stg[w][st][ROW_BYTES]);

        float acc = 0.0f;
#pragma unroll
        for (int k = 0; k < 4; ++k) {
            const int c = k * 32 + lane;
            const uint4 dv = du[c];
            const uint4 av = au[c];
            const __half2* dh = reinterpret_cast<const __half2*>(&dv);
            const __half2* ah = reinterpret_cast<const __half2*>(&av);
#pragma unroll
            for (int j = 0; j < 4; ++j) {
                const float2 df = __half22float2(dh[j]);
                const float2 af = __half22float2(ah[j]);
                acc = fmaf(df.x, af.x, acc);
                acc = fmaf(df.y, af.y, acc);
            }
        }
#pragma unroll
        for (int o = 16; o; o >>= 1)
            acc += __shfl_down_sync(0xffffffffu, acc, o);

        if (lane == 0)
            out[qbase + i] = fmaxf(fmaf(bt, acc, mu[si[i]]), 0.0f);

        __syncwarp();   // all lanes done with stage st (values consumed)

        if (i + 2 < QK_QPW && lane == 0)
            issue(i + 2, st);
    }
}

// ---------------------------------------------------------------------------
extern "C" void kernel_launch(void* const* d_in, const int* in_sizes, int n_in,
                              void* d_out, int out_size) {
    const int*   t     = (const int*)d_in[0];
    const int*   s     = (const int*)d_in[1];
    const int*   obs   = (const int*)d_in[2];
    const float* alpha = (const float*)d_in[3];
    const float* beta  = (const float*)d_in[4];
    const float* mu    = (const float*)d_in[5];
    float* out = (float*)d_out;
    (void)in_sizes; (void)n_in; (void)out_size;

    prep_kernel<<<NSCAN_BLK + NTRANS_BLK, 256>>>(alpha, obs, beta);
    query_kernel<<<QK_BLOCKS, 128>>>(t, s, beta, mu, out);
}